// round 5
// baseline (speedup 1.0000x reference)
#include <cuda_runtime.h>

// HopfieldNetwork: B=8, N=4096, ITERS=10 asynchronous sweeps.
// R5: single barrier per flip. Candidates are generated from REGISTER state
// (each thread owns 8 z values + their sign/y bits); a per-sweep pos_of[]
// table (neuron -> position in this sweep's permutation) replaces the
// position-ordered shared scan. Earliest-position candidate selected via
// redux.sync.min + 16 double-buffered slots. z is int64 fixed point
// (scale 2^-61); update terms f2i_rz(w * +-2^62) are bit-identical to R4.

constexpr int NN  = 4096;
constexpr int TPB = 512;
constexpr int ZPT = 8;            // z elements per thread
constexpr unsigned INF = 0x7FFFFFFFu;

__device__ long long g_z[8 * NN];                      // z0, int64 scale 2^61
__device__ __align__(16) unsigned char g_xsign[NN];    // bit b = (x[b][c] < 0)

// ---------------------------------------------------------------------------
// Kernel 0: pack x signs into one byte per column.
// ---------------------------------------------------------------------------
__global__ void pack_x(const float* __restrict__ x, int B)
{
    const int c = blockIdx.x * 256 + threadIdx.x;
    unsigned v = 0;
#pragma unroll
    for (int b = 0; b < 8; b++)
        if (b < B && x[(size_t)b * NN + c] < 0.f) v |= 1u << b;
    g_xsign[c] = (unsigned char)v;
}

// ---------------------------------------------------------------------------
// Kernel 1: z0[b][row] = sum_c W[row][c] * x[b][c], int64 fixed point.
// One block per row. val = w * (+-2^61) exact in fp32; cvt.rzi truncates.
// ---------------------------------------------------------------------------
__global__ void __launch_bounds__(256) gemv_init(const float* __restrict__ W,
                                                 int B)
{
    const int row  = blockIdx.x;
    const int tid  = threadIdx.x;
    const int base = tid * 16;
    const int lane = tid & 31, wid = tid >> 5;

    const uint4 sb4 = *reinterpret_cast<const uint4*>(g_xsign + base);
    const unsigned sb[4] = {sb4.x, sb4.y, sb4.z, sb4.w};

    const float4* w4 = reinterpret_cast<const float4*>(W + (size_t)row * NN + base);
    const float4 wa = w4[0], wb = w4[1], wc = w4[2], wd = w4[3];
    const float wv[16] = {wa.x, wa.y, wa.z, wa.w,  wb.x, wb.y, wb.z, wb.w,
                          wc.x, wc.y, wc.z, wc.w,  wd.x, wd.y, wd.z, wd.w};

    long long acc[8];
#pragma unroll
    for (int b = 0; b < 8; b++) acc[b] = 0ll;

#pragma unroll
    for (int k = 0; k < 16; k++) {
        const unsigned byte = (sb[k >> 2] >> (8 * (k & 3))) & 0xFFu;
        const float w = wv[k];
#pragma unroll
        for (int b = 0; b < 8; b++) {
            const float fs = ((byte >> b) & 1u) ? -0x1.0p61f : 0x1.0p61f;
            acc[b] += __float2ll_rz(w * fs);
        }
    }

#pragma unroll
    for (int b = 0; b < 8; b++) {
#pragma unroll
        for (int off = 16; off > 0; off >>= 1)
            acc[b] += __shfl_down_sync(0xffffffffu, acc[b], off);
    }
    __shared__ long long red[8][8];
    if (lane == 0) {
#pragma unroll
        for (int b = 0; b < 8; b++) red[wid][b] = acc[b];
    }
    __syncthreads();
    if (tid < 8) {
        long long s = 0ll;
#pragma unroll
        for (int w2 = 0; w2 < 8; w2++) s += red[w2][tid];
        if (tid < B) g_z[tid * NN + row] = s;
    }
}

// ---------------------------------------------------------------------------
// Kernel 2: one block per sample, one barrier per flip.
// Key pack: bits[0]=nb(z<0), [1:13]=neuron i, [13:25]=pos-in-sweep.
// ---------------------------------------------------------------------------
__global__ void __launch_bounds__(TPB) hopfield_seq(
    const float* __restrict__ W,
    const float* __restrict__ x,
    const int*   __restrict__ perms,
    float*       __restrict__ out,
    int iters)
{
    const int b    = blockIdx.x;
    const int tid  = threadIdx.x;
    const int lane = tid & 31;
    const int wid  = tid >> 5;          // 16 warps
    const int base = tid * ZPT;

    __shared__ __align__(16) unsigned short pos_of[NN];   // neuron -> pos
    __shared__ __align__(16) int sh_slot[2][16];

    // ---- load z slice and x signs into registers ----
    long long z[ZPT];
    {
        const long long* gz = g_z + (size_t)b * NN + base;
#pragma unroll
        for (int k = 0; k < ZPT; k++) z[k] = gz[k];
    }

    unsigned ym = 0;   // bit k = (y[base+k] < 0)
    {
        const float4* x4 = reinterpret_cast<const float4*>(x + (size_t)b * NN + base);
        const float4 xa = x4[0], xb = x4[1];
        const float xv[8] = {xa.x, xa.y, xa.z, xa.w, xb.x, xb.y, xb.z, xb.w};
#pragma unroll
        for (int k = 0; k < ZPT; k++)
            ym |= (__float_as_uint(xv[k]) >> 31) << k;
    }

    unsigned sgn = 0;  // bit k = (z[base+k] < 0)
#pragma unroll
    for (int k = 0; k < ZPT; k++)
        sgn |= (unsigned)((unsigned long long)z[k] >> 63) << k;

    const int* pb = perms + (size_t)b * iters * NN;
    int parity = 0;

    for (int sweep = 0; sweep < iters; sweep++) {
        // ---- rebuild neuron -> position table for this sweep ----
        const int* ps = pb + sweep * NN;
        {
            const int4* p4 = reinterpret_cast<const int4*>(ps + tid * 8);
            const int4 a = p4[0], c = p4[1];
            const int p0 = tid * 8;
            pos_of[a.x] = (unsigned short)(p0 + 0);
            pos_of[a.y] = (unsigned short)(p0 + 1);
            pos_of[a.z] = (unsigned short)(p0 + 2);
            pos_of[a.w] = (unsigned short)(p0 + 3);
            pos_of[c.x] = (unsigned short)(p0 + 4);
            pos_of[c.y] = (unsigned short)(p0 + 5);
            pos_of[c.z] = (unsigned short)(p0 + 6);
            pos_of[c.w] = (unsigned short)(p0 + 7);
        }
        int lastp = -1;
        __syncthreads();                         // pos_of visible

        // ---- initial candidates for this sweep (from register state) ----
        {
            const unsigned m = (sgn ^ ym) & 0xFFu;
            unsigned key = INF;
#pragma unroll
            for (int k = 0; k < ZPT; k++) {
                if ((m >> k) & 1u) {
                    const int p = pos_of[base + k];
                    const unsigned cand = ((unsigned)p << 13)
                                        | ((unsigned)(base + k) << 1)
                                        | ((sgn >> k) & 1u);
                    key = min(key, cand);
                }
            }
            const unsigned wmin = __reduce_min_sync(0xffffffffu, key);
            if (lane == 0) sh_slot[parity][wid] = (int)wmin;
        }
        __syncthreads();                         // slots visible

        // ---- flip rounds: one barrier each ----
        for (;;) {
            const int4 s0 = reinterpret_cast<const int4*>(sh_slot[parity])[0];
            const int4 s1 = reinterpret_cast<const int4*>(sh_slot[parity])[1];
            const int4 s2 = reinterpret_cast<const int4*>(sh_slot[parity])[2];
            const int4 s3 = reinterpret_cast<const int4*>(sh_slot[parity])[3];
            parity ^= 1;
            const int m01 = min(min(min(s0.x, s0.y), min(s0.z, s0.w)),
                                min(min(s1.x, s1.y), min(s1.z, s1.w)));
            const int m23 = min(min(min(s2.x, s2.y), min(s2.z, s2.w)),
                                min(min(s3.x, s3.y), min(s3.z, s3.w)));
            const int mk = min(m01, m23);
            if (mk == (int)INF) break;           // sweep finished

            const int fi = (mk >> 1) & 0xFFF;
            const int nb = mk & 1;
            lastp = mk >> 13;

            // ---- W row load (critical) ----
            const float4* w4 =
                reinterpret_cast<const float4*>(W + (size_t)fi * NN + base);
            const float4 wa = w4[0], wb_ = w4[1];

            // ---- prefetch runner-up candidate's row ----
            {
                int e0 = (s0.x == mk) ? (int)INF : s0.x;
                int e1 = (s0.y == mk) ? (int)INF : s0.y;
                int e2 = (s0.z == mk) ? (int)INF : s0.z;
                int e3 = (s0.w == mk) ? (int)INF : s0.w;
                int e4 = (s1.x == mk) ? (int)INF : s1.x;
                int e5 = (s1.y == mk) ? (int)INF : s1.y;
                int e6 = (s1.z == mk) ? (int)INF : s1.z;
                int e7 = (s1.w == mk) ? (int)INF : s1.w;
                int e8 = (s2.x == mk) ? (int)INF : s2.x;
                int e9 = (s2.y == mk) ? (int)INF : s2.y;
                int ea = (s2.z == mk) ? (int)INF : s2.z;
                int eb = (s2.w == mk) ? (int)INF : s2.w;
                int ec = (s3.x == mk) ? (int)INF : s3.x;
                int ed = (s3.y == mk) ? (int)INF : s3.y;
                int ee = (s3.z == mk) ? (int)INF : s3.z;
                int ef = (s3.w == mk) ? (int)INF : s3.w;
                const int mk2 = min(min(min(min(e0, e1), min(e2, e3)),
                                        min(min(e4, e5), min(e6, e7))),
                                    min(min(min(e8, e9), min(ea, eb)),
                                        min(min(ec, ed), min(ee, ef))));
                if (mk2 != (int)INF) {
                    const char* p2 = reinterpret_cast<const char*>(
                        W + (size_t)((mk2 >> 1) & 0xFFF) * NN + base);
                    asm volatile("prefetch.global.L1 [%0];" :: "l"(p2));
                }
            }

            // owner records the flip in its y bits
            if (tid == (fi >> 3)) ym ^= 1u << (fi & 7);

            // ---- int64 axpy; fd = +-2 folded into +-2^62 (exact fp32) ----
            const float fscale = nb ? -0x1.0p62f : 0x1.0p62f;
            const float wv[ZPT] = {wa.x, wa.y, wa.z, wa.w,
                                   wb_.x, wb_.y, wb_.z, wb_.w};
#pragma unroll
            for (int k = 0; k < ZPT; k++)
                z[k] += __float2ll_rz(wv[k] * fscale);

            // ---- new signs + candidate regeneration from registers ----
            sgn = 0;
#pragma unroll
            for (int k = 0; k < ZPT; k++)
                sgn |= (unsigned)((unsigned long long)z[k] >> 63) << k;

            {
                const unsigned m = (sgn ^ ym) & 0xFFu;
                unsigned key = INF;
#pragma unroll
                for (int k = 0; k < ZPT; k++) {
                    if ((m >> k) & 1u) {
                        const int p = pos_of[base + k];
                        if (p > lastp) {
                            const unsigned cand = ((unsigned)p << 13)
                                                | ((unsigned)(base + k) << 1)
                                                | ((sgn >> k) & 1u);
                            key = min(key, cand);
                        }
                    }
                }
                const unsigned wmin = __reduce_min_sync(0xffffffffu, key);
                if (lane == 0) sh_slot[parity][wid] = (int)wmin;
            }
            __syncthreads();                     // the single barrier
        }
    }

    // ---- write y from register state ----
    float ov[ZPT];
#pragma unroll
    for (int k = 0; k < ZPT; k++)
        ov[k] = ((ym >> k) & 1u) ? -1.0f : 1.0f;
    float4* o4 = reinterpret_cast<float4*>(out + (size_t)b * NN + base);
    o4[0] = make_float4(ov[0], ov[1], ov[2], ov[3]);
    o4[1] = make_float4(ov[4], ov[5], ov[6], ov[7]);
}

// ---------------------------------------------------------------------------
extern "C" void kernel_launch(void* const* d_in, const int* in_sizes, int n_in,
                              void* d_out, int out_size)
{
    const float* x     = (const float*)d_in[0];
    const float* W     = (const float*)d_in[1];
    const int*   perms = (const int*)  d_in[2];
    float*       out   = (float*)d_out;

    const int B     = in_sizes[0] / NN;
    const int iters = in_sizes[2] / in_sizes[0];

    pack_x<<<NN / 256, 256>>>(x, B);
    gemv_init<<<NN, 256>>>(W, B);
    hopfield_seq<<<B, TPB>>>(W, x, perms, out, iters);
}

// round 6
// speedup vs baseline: 1.0068x; 1.0068x over previous
#include <cuda_runtime.h>

// HopfieldNetwork: B=8, N=4096, ITERS=10 asynchronous sweeps.
// R6: R5 structure (single barrier per flip, register candidate generation)
// with the per-flip pos_of LDS gather removed: each thread's owned neurons
// are fixed, so their permutation positions are loaded ONCE per sweep and
// kept as pre-packed candidate keys in registers. Per-flip candidate regen
// is pure register ALU. The `pos > lastp` filter is `cand > winner_key`
// (pos is the high key field; the winner can't re-candidate since its own
// z is unchanged, diag(W)=0). z is int64 fixed point (scale 2^-61).

constexpr int NN  = 4096;
constexpr int TPB = 512;
constexpr int ZPT = 8;            // z elements per thread
constexpr int INF = 0x7FFFFFFF;

__device__ long long g_z[8 * NN];                      // z0, int64 scale 2^61
__device__ __align__(16) unsigned char g_xsign[NN];    // bit b = (x[b][c] < 0)

// ---------------------------------------------------------------------------
// Kernel 0: pack x signs into one byte per column.
// ---------------------------------------------------------------------------
__global__ void pack_x(const float* __restrict__ x, int B)
{
    const int c = blockIdx.x * 256 + threadIdx.x;
    unsigned v = 0;
#pragma unroll
    for (int b = 0; b < 8; b++)
        if (b < B && x[(size_t)b * NN + c] < 0.f) v |= 1u << b;
    g_xsign[c] = (unsigned char)v;
}

// ---------------------------------------------------------------------------
// Kernel 1: z0[b][row] = sum_c W[row][c] * x[b][c], int64 fixed point.
// One block per row. val = w * (+-2^61) exact in fp32; cvt.rzi truncates.
// ---------------------------------------------------------------------------
__global__ void __launch_bounds__(256) gemv_init(const float* __restrict__ W,
                                                 int B)
{
    const int row  = blockIdx.x;
    const int tid  = threadIdx.x;
    const int base = tid * 16;
    const int lane = tid & 31, wid = tid >> 5;

    const uint4 sb4 = *reinterpret_cast<const uint4*>(g_xsign + base);
    const unsigned sb[4] = {sb4.x, sb4.y, sb4.z, sb4.w};

    const float4* w4 = reinterpret_cast<const float4*>(W + (size_t)row * NN + base);
    const float4 wa = w4[0], wb = w4[1], wc = w4[2], wd = w4[3];
    const float wv[16] = {wa.x, wa.y, wa.z, wa.w,  wb.x, wb.y, wb.z, wb.w,
                          wc.x, wc.y, wc.z, wc.w,  wd.x, wd.y, wd.z, wd.w};

    long long acc[8];
#pragma unroll
    for (int b = 0; b < 8; b++) acc[b] = 0ll;

#pragma unroll
    for (int k = 0; k < 16; k++) {
        const unsigned byte = (sb[k >> 2] >> (8 * (k & 3))) & 0xFFu;
        const float w = wv[k];
#pragma unroll
        for (int b = 0; b < 8; b++) {
            const float fs = ((byte >> b) & 1u) ? -0x1.0p61f : 0x1.0p61f;
            acc[b] += __float2ll_rz(w * fs);
        }
    }

#pragma unroll
    for (int b = 0; b < 8; b++) {
#pragma unroll
        for (int off = 16; off > 0; off >>= 1)
            acc[b] += __shfl_down_sync(0xffffffffu, acc[b], off);
    }
    __shared__ long long red[8][8];
    if (lane == 0) {
#pragma unroll
        for (int b = 0; b < 8; b++) red[wid][b] = acc[b];
    }
    __syncthreads();
    if (tid < 8) {
        long long s = 0ll;
#pragma unroll
        for (int w2 = 0; w2 < 8; w2++) s += red[w2][tid];
        if (tid < B) g_z[tid * NN + row] = s;
    }
}

// ---------------------------------------------------------------------------
// Kernel 2: one block per sample, one barrier per flip, register candgen.
// Key pack: bits[0]=nb(z<0), [1:13]=neuron i, [13:25]=pos-in-sweep.
// ---------------------------------------------------------------------------
__global__ void __launch_bounds__(TPB) hopfield_seq(
    const float* __restrict__ W,
    const float* __restrict__ x,
    const int*   __restrict__ perms,
    float*       __restrict__ out,
    int iters)
{
    const int b    = blockIdx.x;
    const int tid  = threadIdx.x;
    const int lane = tid & 31;
    const int wid  = tid >> 5;          // 16 warps
    const int base = tid * ZPT;

    __shared__ __align__(16) unsigned short pos_of[NN];   // neuron -> pos
    __shared__ __align__(16) int sh_slot[2][16];

    // ---- load z slice and x signs into registers ----
    long long z[ZPT];
    {
        const long long* gz = g_z + (size_t)b * NN + base;
#pragma unroll
        for (int k = 0; k < ZPT; k++) z[k] = gz[k];
    }

    unsigned ym = 0;   // bit k = (y[base+k] < 0)
    {
        const float4* x4 = reinterpret_cast<const float4*>(x + (size_t)b * NN + base);
        const float4 xa = x4[0], xb = x4[1];
        const float xv[8] = {xa.x, xa.y, xa.z, xa.w, xb.x, xb.y, xb.z, xb.w};
#pragma unroll
        for (int k = 0; k < ZPT; k++)
            ym |= (__float_as_uint(xv[k]) >> 31) << k;
    }

    unsigned sgn = 0;  // bit k = (z[base+k] < 0)
#pragma unroll
    for (int k = 0; k < ZPT; k++)
        sgn |= (unsigned)((unsigned long long)z[k] >> 63) << k;

    const int* pb = perms + (size_t)b * iters * NN;
    int parity = 0;

    for (int sweep = 0; sweep < iters; sweep++) {
        // ---- build neuron -> position table for this sweep ----
        const int* ps = pb + sweep * NN;
        {
            const int4* p4 = reinterpret_cast<const int4*>(ps + tid * 8);
            const int4 a = p4[0], c = p4[1];
            const int p0 = tid * 8;
            pos_of[a.x] = (unsigned short)(p0 + 0);
            pos_of[a.y] = (unsigned short)(p0 + 1);
            pos_of[a.z] = (unsigned short)(p0 + 2);
            pos_of[a.w] = (unsigned short)(p0 + 3);
            pos_of[c.x] = (unsigned short)(p0 + 4);
            pos_of[c.y] = (unsigned short)(p0 + 5);
            pos_of[c.z] = (unsigned short)(p0 + 6);
            pos_of[c.w] = (unsigned short)(p0 + 7);
        }
        __syncthreads();                         // pos_of visible

        // ---- positions of OWNED neurons -> registers, once per sweep ----
        int pkey[ZPT];                           // (pos<<13)|(neuron<<1)
#pragma unroll
        for (int k = 0; k < ZPT; k++)
            pkey[k] = ((int)pos_of[base + k] << 13) | ((base + k) << 1);

        // ---- initial candidates for this sweep ----
        int thr = -1;
        {
            const unsigned m = (sgn ^ ym) & 0xFFu;
            unsigned key = (unsigned)INF;
#pragma unroll
            for (int k = 0; k < ZPT; k++) {
                const unsigned cand = (unsigned)(pkey[k] | (int)((sgn >> k) & 1u));
                if (((m >> k) & 1u) && (int)cand > thr) key = min(key, cand);
            }
            const unsigned wmin = __reduce_min_sync(0xffffffffu, key);
            if (lane == 0) sh_slot[parity][wid] = (int)wmin;
        }
        __syncthreads();                         // slots visible

        // ---- flip rounds: one barrier each ----
        for (;;) {
            const int4 s0 = reinterpret_cast<const int4*>(sh_slot[parity])[0];
            const int4 s1 = reinterpret_cast<const int4*>(sh_slot[parity])[1];
            const int4 s2 = reinterpret_cast<const int4*>(sh_slot[parity])[2];
            const int4 s3 = reinterpret_cast<const int4*>(sh_slot[parity])[3];
            parity ^= 1;
            const int m01 = min(min(min(s0.x, s0.y), min(s0.z, s0.w)),
                                min(min(s1.x, s1.y), min(s1.z, s1.w)));
            const int m23 = min(min(min(s2.x, s2.y), min(s2.z, s2.w)),
                                min(min(s3.x, s3.y), min(s3.z, s3.w)));
            const int mk = min(m01, m23);
            if (mk == INF) break;                // sweep finished

            const int fi = (mk >> 1) & 0xFFF;
            const int nb = mk & 1;
            thr = mk;                            // pos filter for regen

            // ---- W row load (critical) ----
            const float4* w4 =
                reinterpret_cast<const float4*>(W + (size_t)fi * NN + base);
            const float4 wa = w4[0], wb_ = w4[1];

            // ---- prefetch runner-up candidate's row (off critical path) ----
            {
                int e0 = (s0.x == mk) ? INF : s0.x;
                int e1 = (s0.y == mk) ? INF : s0.y;
                int e2 = (s0.z == mk) ? INF : s0.z;
                int e3 = (s0.w == mk) ? INF : s0.w;
                int e4 = (s1.x == mk) ? INF : s1.x;
                int e5 = (s1.y == mk) ? INF : s1.y;
                int e6 = (s1.z == mk) ? INF : s1.z;
                int e7 = (s1.w == mk) ? INF : s1.w;
                int e8 = (s2.x == mk) ? INF : s2.x;
                int e9 = (s2.y == mk) ? INF : s2.y;
                int ea = (s2.z == mk) ? INF : s2.z;
                int eb = (s2.w == mk) ? INF : s2.w;
                int ec = (s3.x == mk) ? INF : s3.x;
                int ed = (s3.y == mk) ? INF : s3.y;
                int ee = (s3.z == mk) ? INF : s3.z;
                int ef = (s3.w == mk) ? INF : s3.w;
                const int mk2 = min(min(min(min(e0, e1), min(e2, e3)),
                                        min(min(e4, e5), min(e6, e7))),
                                    min(min(min(e8, e9), min(ea, eb)),
                                        min(min(ec, ed), min(ee, ef))));
                if (mk2 != INF) {
                    const char* p2 = reinterpret_cast<const char*>(
                        W + (size_t)((mk2 >> 1) & 0xFFF) * NN + base);
                    asm volatile("prefetch.global.L1 [%0];" :: "l"(p2));
                }
            }

            // owner records the flip in its y bits
            if (tid == (fi >> 3)) ym ^= 1u << (fi & 7);

            // ---- int64 axpy; fd = +-2 folded into +-2^62 (exact fp32) ----
            const float fscale = nb ? -0x1.0p62f : 0x1.0p62f;
            const float wv[ZPT] = {wa.x, wa.y, wa.z, wa.w,
                                   wb_.x, wb_.y, wb_.z, wb_.w};
#pragma unroll
            for (int k = 0; k < ZPT; k++)
                z[k] += __float2ll_rz(wv[k] * fscale);

            // ---- new signs + register candidate regeneration ----
            sgn = 0;
#pragma unroll
            for (int k = 0; k < ZPT; k++)
                sgn |= (unsigned)((unsigned long long)z[k] >> 63) << k;

            {
                const unsigned m = (sgn ^ ym) & 0xFFu;
                unsigned key = (unsigned)INF;
#pragma unroll
                for (int k = 0; k < ZPT; k++) {
                    const unsigned cand = (unsigned)(pkey[k] | (int)((sgn >> k) & 1u));
                    if (((m >> k) & 1u) && (int)cand > thr) key = min(key, cand);
                }
                const unsigned wmin = __reduce_min_sync(0xffffffffu, key);
                if (lane == 0) sh_slot[parity][wid] = (int)wmin;
            }
            __syncthreads();                     // the single barrier
        }
    }

    // ---- write y from register state ----
    float ov[ZPT];
#pragma unroll
    for (int k = 0; k < ZPT; k++)
        ov[k] = ((ym >> k) & 1u) ? -1.0f : 1.0f;
    float4* o4 = reinterpret_cast<float4*>(out + (size_t)b * NN + base);
    o4[0] = make_float4(ov[0], ov[1], ov[2], ov[3]);
    o4[1] = make_float4(ov[4], ov[5], ov[6], ov[7]);
}

// ---------------------------------------------------------------------------
extern "C" void kernel_launch(void* const* d_in, const int* in_sizes, int n_in,
                              void* d_out, int out_size)
{
    const float* x     = (const float*)d_in[0];
    const float* W     = (const float*)d_in[1];
    const int*   perms = (const int*)  d_in[2];
    float*       out   = (float*)d_out;

    const int B     = in_sizes[0] / NN;
    const int iters = in_sizes[2] / in_sizes[0];

    pack_x<<<NN / 256, 256>>>(x, B);
    gemv_init<<<NN, 256>>>(W, B);
    hopfield_seq<<<B, TPB>>>(W, x, perms, out, iters);
}

// round 7
// speedup vs baseline: 1.2436x; 1.2351x over previous
#include <cuda_runtime.h>

// HopfieldNetwork: B=8, N=4096, ITERS=10 asynchronous sweeps.
// R7: speculative register-resident W row for the predicted next winner
// (runner-up by position) -- on prediction hits the axpy reads registers,
// removing both the W-row load latency and its L1 wavefronts from the
// critical path. Decode is lane-parallel (one slot per lane + redux.min)
// instead of a per-thread 31-op min tree. One barrier per flip. z is int64
// fixed point (scale 2^-61); update terms f2i_rz(w * +-2^62) bit-identical
// to R4/R6 (rel_err stayed 0.0).

constexpr int NN  = 4096;
constexpr int TPB = 512;
constexpr int ZPT = 8;            // z elements per thread
constexpr int INF = 0x7FFFFFFF;

__device__ long long g_z[8 * NN];                      // z0, int64 scale 2^61
__device__ __align__(16) unsigned char g_xsign[NN];    // bit b = (x[b][c] < 0)

// ---------------------------------------------------------------------------
// Kernel 0: pack x signs into one byte per column.
// ---------------------------------------------------------------------------
__global__ void pack_x(const float* __restrict__ x, int B)
{
    const int c = blockIdx.x * 256 + threadIdx.x;
    unsigned v = 0;
#pragma unroll
    for (int b = 0; b < 8; b++)
        if (b < B && x[(size_t)b * NN + c] < 0.f) v |= 1u << b;
    g_xsign[c] = (unsigned char)v;
}

// ---------------------------------------------------------------------------
// Kernel 1: z0[b][row] = sum_c W[row][c] * x[b][c], int64 fixed point.
// One block per row. val = w * (+-2^61) exact in fp32; cvt.rzi truncates.
// ---------------------------------------------------------------------------
__global__ void __launch_bounds__(256) gemv_init(const float* __restrict__ W,
                                                 int B)
{
    const int row  = blockIdx.x;
    const int tid  = threadIdx.x;
    const int base = tid * 16;
    const int lane = tid & 31, wid = tid >> 5;

    const uint4 sb4 = *reinterpret_cast<const uint4*>(g_xsign + base);
    const unsigned sb[4] = {sb4.x, sb4.y, sb4.z, sb4.w};

    const float4* w4 = reinterpret_cast<const float4*>(W + (size_t)row * NN + base);
    const float4 wa = w4[0], wb = w4[1], wc = w4[2], wd = w4[3];
    const float wv[16] = {wa.x, wa.y, wa.z, wa.w,  wb.x, wb.y, wb.z, wb.w,
                          wc.x, wc.y, wc.z, wc.w,  wd.x, wd.y, wd.z, wd.w};

    long long acc[8];
#pragma unroll
    for (int b = 0; b < 8; b++) acc[b] = 0ll;

#pragma unroll
    for (int k = 0; k < 16; k++) {
        const unsigned byte = (sb[k >> 2] >> (8 * (k & 3))) & 0xFFu;
        const float w = wv[k];
#pragma unroll
        for (int b = 0; b < 8; b++) {
            const float fs = ((byte >> b) & 1u) ? -0x1.0p61f : 0x1.0p61f;
            acc[b] += __float2ll_rz(w * fs);
        }
    }

#pragma unroll
    for (int b = 0; b < 8; b++) {
#pragma unroll
        for (int off = 16; off > 0; off >>= 1)
            acc[b] += __shfl_down_sync(0xffffffffu, acc[b], off);
    }
    __shared__ long long red[8][8];
    if (lane == 0) {
#pragma unroll
        for (int b = 0; b < 8; b++) red[wid][b] = acc[b];
    }
    __syncthreads();
    if (tid < 8) {
        long long s = 0ll;
#pragma unroll
        for (int w2 = 0; w2 < 8; w2++) s += red[w2][tid];
        if (tid < B) g_z[tid * NN + row] = s;
    }
}

// ---------------------------------------------------------------------------
// Kernel 2: one block per sample, one barrier per flip.
// Key pack: bits[0]=nb(z<0), [1:13]=neuron i, [13:25]=pos-in-sweep.
// ---------------------------------------------------------------------------
__global__ void __launch_bounds__(TPB) hopfield_seq(
    const float* __restrict__ W,
    const float* __restrict__ x,
    const int*   __restrict__ perms,
    float*       __restrict__ out,
    int iters)
{
    const int b    = blockIdx.x;
    const int tid  = threadIdx.x;
    const int lane = tid & 31;
    const int wid  = tid >> 5;          // 16 warps
    const int base = tid * ZPT;

    __shared__ __align__(16) unsigned short pos_of[NN];   // neuron -> pos
    __shared__ __align__(16) int sh_slot[2][16];

    // ---- load z slice and x signs into registers ----
    long long z[ZPT];
    {
        const long long* gz = g_z + (size_t)b * NN + base;
#pragma unroll
        for (int k = 0; k < ZPT; k++) z[k] = gz[k];
    }

    unsigned ym = 0;   // bit k = (y[base+k] < 0)
    {
        const float4* x4 = reinterpret_cast<const float4*>(x + (size_t)b * NN + base);
        const float4 xa = x4[0], xb = x4[1];
        const float xv[8] = {xa.x, xa.y, xa.z, xa.w, xb.x, xb.y, xb.z, xb.w};
#pragma unroll
        for (int k = 0; k < ZPT; k++)
            ym |= (__float_as_uint(xv[k]) >> 31) << k;
    }

    unsigned sgn = 0;  // bit k = (z[base+k] < 0)
#pragma unroll
    for (int k = 0; k < ZPT; k++)
        sgn |= (unsigned)((unsigned long long)z[k] >> 63) << k;

    const int* pb = perms + (size_t)b * iters * NN;
    int parity  = 0;
    int spec_id = -1;          // neuron whose W row sits in specv
    float specv[ZPT];
#pragma unroll
    for (int k = 0; k < ZPT; k++) specv[k] = 0.f;

    for (int sweep = 0; sweep < iters; sweep++) {
        // ---- build neuron -> position table for this sweep ----
        const int* ps = pb + sweep * NN;
        {
            const int4* p4 = reinterpret_cast<const int4*>(ps + tid * 8);
            const int4 a = p4[0], c = p4[1];
            const int p0 = tid * 8;
            pos_of[a.x] = (unsigned short)(p0 + 0);
            pos_of[a.y] = (unsigned short)(p0 + 1);
            pos_of[a.z] = (unsigned short)(p0 + 2);
            pos_of[a.w] = (unsigned short)(p0 + 3);
            pos_of[c.x] = (unsigned short)(p0 + 4);
            pos_of[c.y] = (unsigned short)(p0 + 5);
            pos_of[c.z] = (unsigned short)(p0 + 6);
            pos_of[c.w] = (unsigned short)(p0 + 7);
        }
        __syncthreads();                         // pos_of visible

        // ---- positions of OWNED neurons -> registers, once per sweep ----
        int pkey[ZPT];                           // (pos<<13)|(neuron<<1)
#pragma unroll
        for (int k = 0; k < ZPT; k++)
            pkey[k] = ((int)pos_of[base + k] << 13) | ((base + k) << 1);

        // ---- initial candidates for this sweep ----
        {
            const unsigned m = (sgn ^ ym) & 0xFFu;
            unsigned key = (unsigned)INF;
#pragma unroll
            for (int k = 0; k < ZPT; k++) {
                const unsigned cand = (unsigned)(pkey[k] | (int)((sgn >> k) & 1u));
                if ((m >> k) & 1u) key = min(key, cand);
            }
            const unsigned wmin = __reduce_min_sync(0xffffffffu, key);
            if (lane == 0) sh_slot[parity][wid] = (int)wmin;
        }
        __syncthreads();                         // slots visible

        int thr = -1;

        // ---- flip rounds: one barrier each ----
        for (;;) {
            // lane-parallel decode: one slot per lane, redux for winner/runner
            const int a  = (lane < 16) ? sh_slot[parity][lane] : INF;
            parity ^= 1;
            const int mk = (int)__reduce_min_sync(0xffffffffu, (unsigned)a);
            if (mk == INF) break;                // sweep finished

            const int e  = (a == mk) ? INF : a;
            const int ru = (int)__reduce_min_sync(0xffffffffu, (unsigned)e);

            const int fi = (mk >> 1) & 0xFFF;
            const int nb = mk & 1;
            thr = mk;

            // ---- W row: registers on spec hit, demand load on miss ----
            float wv[ZPT];
            if (fi == spec_id) {                 // uniform branch
#pragma unroll
                for (int k = 0; k < ZPT; k++) wv[k] = specv[k];
            } else {
                const float4* w4 =
                    reinterpret_cast<const float4*>(W + (size_t)fi * NN + base);
                const float4 wa = __ldg(w4), wb_ = __ldg(w4 + 1);
                wv[0] = wa.x;  wv[1] = wa.y;  wv[2] = wa.z;  wv[3] = wa.w;
                wv[4] = wb_.x; wv[5] = wb_.y; wv[6] = wb_.z; wv[7] = wb_.w;
            }

            // ---- speculative load of runner-up's row for NEXT round ----
            const int nsid = (ru != INF) ? ((ru >> 1) & 0xFFF) : -1;
            if (nsid >= 0) {                     // uniform branch
                const float4* s4 =
                    reinterpret_cast<const float4*>(W + (size_t)nsid * NN + base);
                const float4 sa = __ldg(s4), sb_ = __ldg(s4 + 1);
                specv[0] = sa.x;  specv[1] = sa.y;  specv[2] = sa.z;  specv[3] = sa.w;
                specv[4] = sb_.x; specv[5] = sb_.y; specv[6] = sb_.z; specv[7] = sb_.w;
            }
            spec_id = nsid;

            // owner records the flip in its y bits
            if (tid == (fi >> 3)) ym ^= 1u << (fi & 7);

            // ---- int64 axpy; fd = +-2 folded into +-2^62 (exact fp32) ----
            const float fscale = nb ? -0x1.0p62f : 0x1.0p62f;
#pragma unroll
            for (int k = 0; k < ZPT; k++)
                z[k] += __float2ll_rz(wv[k] * fscale);

            // ---- new signs + register candidate regeneration ----
            sgn = 0;
#pragma unroll
            for (int k = 0; k < ZPT; k++)
                sgn |= (unsigned)((unsigned long long)z[k] >> 63) << k;

            {
                const unsigned m = (sgn ^ ym) & 0xFFu;
                unsigned key = (unsigned)INF;
#pragma unroll
                for (int k = 0; k < ZPT; k++) {
                    const unsigned cand = (unsigned)(pkey[k] | (int)((sgn >> k) & 1u));
                    if (((m >> k) & 1u) && (int)cand > thr) key = min(key, cand);
                }
                const unsigned wmin = __reduce_min_sync(0xffffffffu, key);
                if (lane == 0) sh_slot[parity][wid] = (int)wmin;
            }
            __syncthreads();                     // the single barrier
        }
    }

    // ---- write y from register state ----
    float ov[ZPT];
#pragma unroll
    for (int k = 0; k < ZPT; k++)
        ov[k] = ((ym >> k) & 1u) ? -1.0f : 1.0f;
    float4* o4 = reinterpret_cast<float4*>(out + (size_t)b * NN + base);
    o4[0] = make_float4(ov[0], ov[1], ov[2], ov[3]);
    o4[1] = make_float4(ov[4], ov[5], ov[6], ov[7]);
}

// ---------------------------------------------------------------------------
extern "C" void kernel_launch(void* const* d_in, const int* in_sizes, int n_in,
                              void* d_out, int out_size)
{
    const float* x     = (const float*)d_in[0];
    const float* W     = (const float*)d_in[1];
    const int*   perms = (const int*)  d_in[2];
    float*       out   = (float*)d_out;

    const int B     = in_sizes[0] / NN;
    const int iters = in_sizes[2] / in_sizes[0];

    pack_x<<<NN / 256, 256>>>(x, B);
    gemv_init<<<NN, 256>>>(W, B);
    hopfield_seq<<<B, TPB>>>(W, x, perms, out, iters);
}

// round 9
// speedup vs baseline: 2.9366x; 2.3614x over previous
#include <cuda_runtime.h>

// HopfieldNetwork: B=8, N=4096, ITERS=10 asynchronous sweeps.
// R9 = R8 with the scale bug fixed: g_z is stored at scale 2^40
// (gemv acc = W.y * 2^40), so a flip must add +-2*wq (wq = W*2^40),
// not +-1*wq. Still one IMAD.WIDE per element (multiplier +-2).
// Quantization: wq = rn(W*2^40), |W|max ~1e-3 -> |wq| < 1.1e9 (fits int32);
// per-flip delta error <= 2^-40 in 2W units, random-walking to ~1e-10
// against z ~ 0.01 -- far below the reference's own fp32 noise.

constexpr int NN  = 4096;
constexpr int TPB = 256;
constexpr int ZPT = 16;           // z elements per thread
constexpr int INF = 0x7FFFFFFF;

__device__ long long g_z[8 * NN];                      // z, int64, scale 2^40
__device__ __align__(16) int g_Wq[NN * NN];            // rn(W * 2^40)
__device__ __align__(16) unsigned char g_xsign[NN];    // bit b = (x[b][c] < 0)

// ---------------------------------------------------------------------------
// Kernel 0: quantize W to int32; block 0 also packs x signs.
// w * 2^40 is an exact fp32 exponent shift; f2i_rn rounds once.
// ---------------------------------------------------------------------------
__global__ void __launch_bounds__(256) prep_wq(const float* __restrict__ W,
                                               const float* __restrict__ x,
                                               int B)
{
    const int base = (blockIdx.x * 256 + threadIdx.x) * 16;
    const float4* w4 = reinterpret_cast<const float4*>(W + base);
    int4* o4 = reinterpret_cast<int4*>(g_Wq + base);
#pragma unroll
    for (int g = 0; g < 4; g++) {
        const float4 v = w4[g];
        int4 o;
        o.x = __float2int_rn(v.x * 0x1.0p40f);
        o.y = __float2int_rn(v.y * 0x1.0p40f);
        o.z = __float2int_rn(v.z * 0x1.0p40f);
        o.w = __float2int_rn(v.w * 0x1.0p40f);
        o4[g] = o;
    }
    if (blockIdx.x == 0) {
        for (int c = threadIdx.x * 16; c < threadIdx.x * 16 + 16; c++) {
            unsigned v = 0;
#pragma unroll
            for (int b = 0; b < 8; b++)
                if (b < B && x[(size_t)b * NN + c] < 0.f) v |= 1u << b;
            g_xsign[c] = (unsigned char)v;
        }
    }
}

// ---------------------------------------------------------------------------
// Kernel 1: z0[b][row] = sum_c Wq[row][c] * y[b][c], pure IMAD.WIDE.
// One block per row. Result at scale 2^40.
// ---------------------------------------------------------------------------
__global__ void __launch_bounds__(256) gemv_init(int B)
{
    const int row  = blockIdx.x;
    const int tid  = threadIdx.x;
    const int base = tid * 16;
    const int lane = tid & 31, wid = tid >> 5;

    const uint4 sb4 = *reinterpret_cast<const uint4*>(g_xsign + base);
    const unsigned sb[4] = {sb4.x, sb4.y, sb4.z, sb4.w};

    const int4* w4 = reinterpret_cast<const int4*>(g_Wq + (size_t)row * NN + base);
    const int4 wa = w4[0], wb = w4[1], wc = w4[2], wd = w4[3];
    const int wq[16] = {wa.x, wa.y, wa.z, wa.w,  wb.x, wb.y, wb.z, wb.w,
                        wc.x, wc.y, wc.z, wc.w,  wd.x, wd.y, wd.z, wd.w};

    long long acc[8];
#pragma unroll
    for (int b = 0; b < 8; b++) acc[b] = 0ll;

#pragma unroll
    for (int k = 0; k < 16; k++) {
        const unsigned byte = (sb[k >> 2] >> (8 * (k & 3))) & 0xFFu;
        const int w = wq[k];
#pragma unroll
        for (int b = 0; b < 8; b++) {
            const int yb = 1 - 2 * (int)((byte >> b) & 1u);
            acc[b] += (long long)w * yb;          // IMAD.WIDE
        }
    }

#pragma unroll
    for (int b = 0; b < 8; b++) {
#pragma unroll
        for (int off = 16; off > 0; off >>= 1)
            acc[b] += __shfl_down_sync(0xffffffffu, acc[b], off);
    }
    __shared__ long long red[8][8];
    if (lane == 0) {
#pragma unroll
        for (int b = 0; b < 8; b++) red[wid][b] = acc[b];
    }
    __syncthreads();
    if (tid < 8) {
        long long s = 0ll;
#pragma unroll
        for (int w2 = 0; w2 < 8; w2++) s += red[w2][tid];
        if (tid < B) g_z[tid * NN + row] = s;
    }
}

// ---------------------------------------------------------------------------
// Kernel 2: one block per sample, one barrier per flip.
// Key pack: bits[0]=nb(z<0), [1:13]=neuron i, [13:25]=pos-in-sweep.
// ---------------------------------------------------------------------------
__global__ void __launch_bounds__(TPB, 1) hopfield_seq(
    const float* __restrict__ x,
    const int*   __restrict__ perms,
    float*       __restrict__ out,
    int iters)
{
    const int b    = blockIdx.x;
    const int tid  = threadIdx.x;
    const int lane = tid & 31;
    const int wid  = tid >> 5;          // 8 warps
    const int base = tid * ZPT;

    __shared__ __align__(16) unsigned short pos_of[NN];   // neuron -> pos
    __shared__ __align__(16) int sh_slot[2][8];

    // ---- load z slice and x signs into registers ----
    long long z[ZPT];
    {
        const long long* gz = g_z + (size_t)b * NN + base;
#pragma unroll
        for (int k = 0; k < ZPT; k++) z[k] = gz[k];
    }

    unsigned ym = 0;   // bit k = (y[base+k] < 0)
    {
        const float4* x4 = reinterpret_cast<const float4*>(x + (size_t)b * NN + base);
#pragma unroll
        for (int g = 0; g < 4; g++) {
            const float4 xv = x4[g];
            ym |= (__float_as_uint(xv.x) >> 31) << (4 * g + 0);
            ym |= (__float_as_uint(xv.y) >> 31) << (4 * g + 1);
            ym |= (__float_as_uint(xv.z) >> 31) << (4 * g + 2);
            ym |= (__float_as_uint(xv.w) >> 31) << (4 * g + 3);
        }
    }

    unsigned sgn = 0;  // bit k = (z[base+k] < 0)
#pragma unroll
    for (int k = 0; k < ZPT; k++)
        sgn |= (unsigned)((unsigned long long)z[k] >> 63) << k;

    const int* pb = perms + (size_t)b * iters * NN;
    int parity  = 0;
    int spec_id = -1;          // neuron whose Wq row sits in specv
    int specv[ZPT];
#pragma unroll
    for (int k = 0; k < ZPT; k++) specv[k] = 0;

    for (int sweep = 0; sweep < iters; sweep++) {
        // ---- build neuron -> position table for this sweep ----
        const int* ps = pb + sweep * NN;
        {
            const int4* p4 = reinterpret_cast<const int4*>(ps + tid * 16);
#pragma unroll
            for (int g = 0; g < 4; g++) {
                const int4 a = p4[g];
                const int p0 = tid * 16 + g * 4;
                pos_of[a.x] = (unsigned short)(p0 + 0);
                pos_of[a.y] = (unsigned short)(p0 + 1);
                pos_of[a.z] = (unsigned short)(p0 + 2);
                pos_of[a.w] = (unsigned short)(p0 + 3);
            }
        }
        __syncthreads();                         // pos_of visible

        // ---- positions of OWNED neurons -> registers, once per sweep ----
        int pkey[ZPT];                           // (pos<<13)|(neuron<<1)
#pragma unroll
        for (int k = 0; k < ZPT; k++)
            pkey[k] = ((int)pos_of[base + k] << 13) | ((base + k) << 1);

        int thr = -1;

        // ---- initial candidates for this sweep ----
        {
            const unsigned m = sgn ^ ym;
            unsigned key = (unsigned)INF;
#pragma unroll
            for (int k = 0; k < ZPT; k++) {
                const unsigned cand = (unsigned)(pkey[k] | (int)((sgn >> k) & 1u));
                if ((m >> k) & 1u) key = min(key, cand);
            }
            const unsigned wmin = __reduce_min_sync(0xffffffffu, key);
            if (lane == 0) sh_slot[parity][wid] = (int)wmin;
        }
        __syncthreads();                         // slots visible

        // ---- flip rounds: one barrier each ----
        for (;;) {
            // lane-parallel decode: one slot per lane, redux for winner/runner
            const int a  = (lane < 8) ? sh_slot[parity][lane] : INF;
            parity ^= 1;
            const int mk = (int)__reduce_min_sync(0xffffffffu, (unsigned)a);
            if (mk == INF) break;                // sweep finished

            const int e  = (a == mk) ? INF : a;
            const int ru = (int)__reduce_min_sync(0xffffffffu, (unsigned)e);

            const int fi = (mk >> 1) & 0xFFF;
            const int nb = mk & 1;
            thr = mk;

            // flip delta is +-2*W; z scale is 2^40, wq = W*2^40 -> add +-2*wq
            const int sfd = 2 - 4 * nb;          // +2 or -2

            // ---- axpy: one IMAD.WIDE per element ----
            if (fi == spec_id) {                 // uniform branch: spec hit
#pragma unroll
                for (int k = 0; k < ZPT; k++)
                    z[k] += (long long)specv[k] * sfd;
            } else {                             // miss: demand load
                const int4* w4 =
                    reinterpret_cast<const int4*>(g_Wq + (size_t)fi * NN + base);
                const int4 da = __ldg(w4 + 0), db = __ldg(w4 + 1);
                const int4 dc = __ldg(w4 + 2), dd = __ldg(w4 + 3);
                const int dv[ZPT] = {da.x, da.y, da.z, da.w,
                                     db.x, db.y, db.z, db.w,
                                     dc.x, dc.y, dc.z, dc.w,
                                     dd.x, dd.y, dd.z, dd.w};
#pragma unroll
                for (int k = 0; k < ZPT; k++)
                    z[k] += (long long)dv[k] * sfd;
            }

            // ---- speculative load of runner-up's row for NEXT round ----
            const int nsid = (ru != INF) ? ((ru >> 1) & 0xFFF) : -1;
            if (nsid >= 0) {                     // uniform branch
                const int4* s4 =
                    reinterpret_cast<const int4*>(g_Wq + (size_t)nsid * NN + base);
                const int4 sa = __ldg(s4 + 0), sb_ = __ldg(s4 + 1);
                const int4 sc = __ldg(s4 + 2), sd_ = __ldg(s4 + 3);
                specv[0]  = sa.x;  specv[1]  = sa.y;  specv[2]  = sa.z;  specv[3]  = sa.w;
                specv[4]  = sb_.x; specv[5]  = sb_.y; specv[6]  = sb_.z; specv[7]  = sb_.w;
                specv[8]  = sc.x;  specv[9]  = sc.y;  specv[10] = sc.z;  specv[11] = sc.w;
                specv[12] = sd_.x; specv[13] = sd_.y; specv[14] = sd_.z; specv[15] = sd_.w;
            }
            spec_id = nsid;

            // owner records the flip in its y bits
            if (tid == (fi >> 4)) ym ^= 1u << (fi & 15);

            // ---- new signs + register candidate regeneration ----
            sgn = 0;
#pragma unroll
            for (int k = 0; k < ZPT; k++)
                sgn |= (unsigned)((unsigned long long)z[k] >> 63) << k;

            {
                const unsigned m = sgn ^ ym;
                unsigned key = (unsigned)INF;
#pragma unroll
                for (int k = 0; k < ZPT; k++) {
                    const unsigned cand = (unsigned)(pkey[k] | (int)((sgn >> k) & 1u));
                    if (((m >> k) & 1u) && (int)cand > thr) key = min(key, cand);
                }
                const unsigned wmin = __reduce_min_sync(0xffffffffu, key);
                if (lane == 0) sh_slot[parity][wid] = (int)wmin;
            }
            __syncthreads();                     // the single barrier
        }
    }

    // ---- write y from register state ----
    float4* o4 = reinterpret_cast<float4*>(out + (size_t)b * NN + base);
#pragma unroll
    for (int g = 0; g < 4; g++) {
        float4 o;
        o.x = ((ym >> (4 * g + 0)) & 1u) ? -1.0f : 1.0f;
        o.y = ((ym >> (4 * g + 1)) & 1u) ? -1.0f : 1.0f;
        o.z = ((ym >> (4 * g + 2)) & 1u) ? -1.0f : 1.0f;
        o.w = ((ym >> (4 * g + 3)) & 1u) ? -1.0f : 1.0f;
        o4[g] = o;
    }
}

// ---------------------------------------------------------------------------
extern "C" void kernel_launch(void* const* d_in, const int* in_sizes, int n_in,
                              void* d_out, int out_size)
{
    const float* x     = (const float*)d_in[0];
    const float* W     = (const float*)d_in[1];
    const int*   perms = (const int*)  d_in[2];
    float*       out   = (float*)d_out;

    const int B     = in_sizes[0] / NN;
    const int iters = in_sizes[2] / in_sizes[0];

    prep_wq<<<NN * NN / (256 * 16), 256>>>(W, x, B);
    gemv_init<<<NN, 256>>>(B);
    hopfield_seq<<<B, TPB>>>(x, perms, out, iters);
}

// round 10
// speedup vs baseline: 3.6085x; 1.2288x over previous
#include <cuda_runtime.h>

// HopfieldNetwork: B=8, N=4096, ITERS=10 asynchronous sweeps.
// R10 = R9 (int32-quantized W, scale 2^40; one IMAD.WIDE per element) with:
//  (a) static per-sweep candidate keys: ckey[k] = pkey[k] | !y_sign and
//      zmask[k] = y_sign<<31 are z-independent, so per-round candgen is just
//      (z_hi ^ zmask) < 0 && ckey > thr -> min. The per-round sign-bitmask
//      rebuild is gone. Flipped elements keep stale ckey/zmask but are
//      excluded by ckey > thr for the rest of the sweep (ckey == thr).
//  (b) 3rd-candidate L1 prefetch: winner is 2nd-ranked -> register spec hit;
//      3rd-ranked -> L1 hit via prefetch (1 instr/thread covers the row).

constexpr int NN  = 4096;
constexpr int TPB = 256;
constexpr int ZPT = 16;           // z elements per thread
constexpr int INF = 0x7FFFFFFF;

__device__ long long g_z[8 * NN];                      // z, int64, scale 2^40
__device__ __align__(16) int g_Wq[NN * NN];            // rn(W * 2^40)
__device__ __align__(16) unsigned char g_xsign[NN];    // bit b = (x[b][c] < 0)

// ---------------------------------------------------------------------------
// Kernel 0: quantize W to int32; block 0 also packs x signs.
// ---------------------------------------------------------------------------
__global__ void __launch_bounds__(256) prep_wq(const float* __restrict__ W,
                                               const float* __restrict__ x,
                                               int B)
{
    const int base = (blockIdx.x * 256 + threadIdx.x) * 16;
    const float4* w4 = reinterpret_cast<const float4*>(W + base);
    int4* o4 = reinterpret_cast<int4*>(g_Wq + base);
#pragma unroll
    for (int g = 0; g < 4; g++) {
        const float4 v = w4[g];
        int4 o;
        o.x = __float2int_rn(v.x * 0x1.0p40f);
        o.y = __float2int_rn(v.y * 0x1.0p40f);
        o.z = __float2int_rn(v.z * 0x1.0p40f);
        o.w = __float2int_rn(v.w * 0x1.0p40f);
        o4[g] = o;
    }
    if (blockIdx.x == 0) {
        for (int c = threadIdx.x * 16; c < threadIdx.x * 16 + 16; c++) {
            unsigned v = 0;
#pragma unroll
            for (int b = 0; b < 8; b++)
                if (b < B && x[(size_t)b * NN + c] < 0.f) v |= 1u << b;
            g_xsign[c] = (unsigned char)v;
        }
    }
}

// ---------------------------------------------------------------------------
// Kernel 1: z0[b][row] = sum_c Wq[row][c] * y[b][c], pure IMAD.WIDE.
// ---------------------------------------------------------------------------
__global__ void __launch_bounds__(256) gemv_init(int B)
{
    const int row  = blockIdx.x;
    const int tid  = threadIdx.x;
    const int base = tid * 16;
    const int lane = tid & 31, wid = tid >> 5;

    const uint4 sb4 = *reinterpret_cast<const uint4*>(g_xsign + base);
    const unsigned sb[4] = {sb4.x, sb4.y, sb4.z, sb4.w};

    const int4* w4 = reinterpret_cast<const int4*>(g_Wq + (size_t)row * NN + base);
    const int4 wa = w4[0], wb = w4[1], wc = w4[2], wd = w4[3];
    const int wq[16] = {wa.x, wa.y, wa.z, wa.w,  wb.x, wb.y, wb.z, wb.w,
                        wc.x, wc.y, wc.z, wc.w,  wd.x, wd.y, wd.z, wd.w};

    long long acc[8];
#pragma unroll
    for (int b = 0; b < 8; b++) acc[b] = 0ll;

#pragma unroll
    for (int k = 0; k < 16; k++) {
        const unsigned byte = (sb[k >> 2] >> (8 * (k & 3))) & 0xFFu;
        const int w = wq[k];
#pragma unroll
        for (int b = 0; b < 8; b++) {
            const int yb = 1 - 2 * (int)((byte >> b) & 1u);
            acc[b] += (long long)w * yb;          // IMAD.WIDE
        }
    }

#pragma unroll
    for (int b = 0; b < 8; b++) {
#pragma unroll
        for (int off = 16; off > 0; off >>= 1)
            acc[b] += __shfl_down_sync(0xffffffffu, acc[b], off);
    }
    __shared__ long long red[8][8];
    if (lane == 0) {
#pragma unroll
        for (int b = 0; b < 8; b++) red[wid][b] = acc[b];
    }
    __syncthreads();
    if (tid < 8) {
        long long s = 0ll;
#pragma unroll
        for (int w2 = 0; w2 < 8; w2++) s += red[w2][tid];
        if (tid < B) g_z[tid * NN + row] = s;
    }
}

// ---------------------------------------------------------------------------
// Kernel 2: one block per sample, one barrier per flip.
// Key pack: bits[0]=nb(z<0 at flip)=!y_sign, [1:13]=neuron i, [13:25]=pos.
// ---------------------------------------------------------------------------
__global__ void __launch_bounds__(TPB, 1) hopfield_seq(
    const float* __restrict__ x,
    const int*   __restrict__ perms,
    float*       __restrict__ out,
    int iters)
{
    const int b    = blockIdx.x;
    const int tid  = threadIdx.x;
    const int lane = tid & 31;
    const int wid  = tid >> 5;          // 8 warps
    const int base = tid * ZPT;

    __shared__ __align__(16) unsigned short pos_of[NN];   // neuron -> pos
    __shared__ __align__(16) int sh_slot[2][8];

    // ---- load z slice and x signs into registers ----
    long long z[ZPT];
    {
        const long long* gz = g_z + (size_t)b * NN + base;
#pragma unroll
        for (int k = 0; k < ZPT; k++) z[k] = gz[k];
    }

    unsigned ym = 0;   // bit k = (y[base+k] < 0)
    {
        const float4* x4 = reinterpret_cast<const float4*>(x + (size_t)b * NN + base);
#pragma unroll
        for (int g = 0; g < 4; g++) {
            const float4 xv = x4[g];
            ym |= (__float_as_uint(xv.x) >> 31) << (4 * g + 0);
            ym |= (__float_as_uint(xv.y) >> 31) << (4 * g + 1);
            ym |= (__float_as_uint(xv.z) >> 31) << (4 * g + 2);
            ym |= (__float_as_uint(xv.w) >> 31) << (4 * g + 3);
        }
    }

    const int* pb = perms + (size_t)b * iters * NN;
    int parity  = 0;
    int spec_id = -1;          // neuron whose Wq row sits in specv
    int specv[ZPT];
#pragma unroll
    for (int k = 0; k < ZPT; k++) specv[k] = 0;

    for (int sweep = 0; sweep < iters; sweep++) {
        // ---- build neuron -> position table for this sweep ----
        const int* ps = pb + sweep * NN;
        {
            const int4* p4 = reinterpret_cast<const int4*>(ps + tid * 16);
#pragma unroll
            for (int g = 0; g < 4; g++) {
                const int4 a = p4[g];
                const int p0 = tid * 16 + g * 4;
                pos_of[a.x] = (unsigned short)(p0 + 0);
                pos_of[a.y] = (unsigned short)(p0 + 1);
                pos_of[a.z] = (unsigned short)(p0 + 2);
                pos_of[a.w] = (unsigned short)(p0 + 3);
            }
        }
        __syncthreads();                         // pos_of visible

        // ---- static per-sweep candidate keys + sign-xor masks ----
        int ckey[ZPT];      // (pos<<13)|(neuron<<1)|(!y_sign)
        int zmask[ZPT];     // y_sign << 31
#pragma unroll
        for (int k = 0; k < ZPT; k++) {
            const int yb = (int)((ym >> k) & 1u);
            ckey[k]  = ((int)pos_of[base + k] << 13) | ((base + k) << 1) | (yb ^ 1);
            zmask[k] = yb << 31;
        }

        int thr = -1;

        // ---- initial candidates for this sweep ----
        {
            unsigned key = (unsigned)INF;
#pragma unroll
            for (int k = 0; k < ZPT; k++) {
                const int t = (int)((unsigned long long)z[k] >> 32) ^ zmask[k];
                if (t < 0) key = min(key, (unsigned)ckey[k]);
            }
            const unsigned wmin = __reduce_min_sync(0xffffffffu, key);
            if (lane == 0) sh_slot[parity][wid] = (int)wmin;
        }
        __syncthreads();                         // slots visible

        // ---- flip rounds: one barrier each ----
        for (;;) {
            // lane-parallel decode: one slot per lane, redux for top-3
            const int a  = (lane < 8) ? sh_slot[parity][lane] : INF;
            parity ^= 1;
            const int mk = (int)__reduce_min_sync(0xffffffffu, (unsigned)a);
            if (mk == INF) break;                // sweep finished

            const int e  = (a == mk) ? INF : a;
            const int r2 = (int)__reduce_min_sync(0xffffffffu, (unsigned)e);

            const int fi = (mk >> 1) & 0xFFF;
            const int nb = mk & 1;
            thr = mk;

            // flip delta is +-2*W at scale 2^40 -> add +-2*wq
            const int sfd = 2 - 4 * nb;

            // ---- axpy: one IMAD.WIDE per element ----
            if (fi == spec_id) {                 // uniform branch: spec hit
#pragma unroll
                for (int k = 0; k < ZPT; k++)
                    z[k] += (long long)specv[k] * sfd;
            } else {                             // miss: demand load
                const int4* w4 =
                    reinterpret_cast<const int4*>(g_Wq + (size_t)fi * NN + base);
                const int4 da = __ldg(w4 + 0), db = __ldg(w4 + 1);
                const int4 dc = __ldg(w4 + 2), dd = __ldg(w4 + 3);
                const int dv[ZPT] = {da.x, da.y, da.z, da.w,
                                     db.x, db.y, db.z, db.w,
                                     dc.x, dc.y, dc.z, dc.w,
                                     dd.x, dd.y, dd.z, dd.w};
#pragma unroll
                for (int k = 0; k < ZPT; k++)
                    z[k] += (long long)dv[k] * sfd;
            }

            // ---- speculative register load of 2nd candidate's row ----
            const int nsid = (r2 != INF) ? ((r2 >> 1) & 0xFFF) : -1;
            if (nsid >= 0) {                     // uniform branch
                const int4* s4 =
                    reinterpret_cast<const int4*>(g_Wq + (size_t)nsid * NN + base);
                const int4 sa = __ldg(s4 + 0), sb_ = __ldg(s4 + 1);
                const int4 sc = __ldg(s4 + 2), sd_ = __ldg(s4 + 3);
                specv[0]  = sa.x;  specv[1]  = sa.y;  specv[2]  = sa.z;  specv[3]  = sa.w;
                specv[4]  = sb_.x; specv[5]  = sb_.y; specv[6]  = sb_.z; specv[7]  = sb_.w;
                specv[8]  = sc.x;  specv[9]  = sc.y;  specv[10] = sc.z;  specv[11] = sc.w;
                specv[12] = sd_.x; specv[13] = sd_.y; specv[14] = sd_.z; specv[15] = sd_.w;
            }
            spec_id = nsid;

            // ---- L1 prefetch of 3rd candidate's row (off critical path) ----
            {
                const int e3 = (a == mk || a == r2) ? INF : a;
                const int r3 = (int)__reduce_min_sync(0xffffffffu, (unsigned)e3);
                if (r3 != INF) {
                    const char* p3 = reinterpret_cast<const char*>(
                        g_Wq + (size_t)((r3 >> 1) & 0xFFF) * NN + base);
                    asm volatile("prefetch.global.L1 [%0];" :: "l"(p3));
                }
            }

            // owner records the flip in its y bits (ckey/zmask stay stale;
            // this element is excluded by ckey > thr for the rest of the sweep)
            if (tid == (fi >> 4)) ym ^= 1u << (fi & 15);

            // ---- candidate regeneration: static keys, sign-xor test ----
            {
                unsigned key = (unsigned)INF;
#pragma unroll
                for (int k = 0; k < ZPT; k++) {
                    const int t = (int)((unsigned long long)z[k] >> 32) ^ zmask[k];
                    if (t < 0 && ckey[k] > thr) key = min(key, (unsigned)ckey[k]);
                }
                const unsigned wmin = __reduce_min_sync(0xffffffffu, key);
                if (lane == 0) sh_slot[parity][wid] = (int)wmin;
            }
            __syncthreads();                     // the single barrier
        }
    }

    // ---- write y from register state ----
    float4* o4 = reinterpret_cast<float4*>(out + (size_t)b * NN + base);
#pragma unroll
    for (int g = 0; g < 4; g++) {
        float4 o;
        o.x = ((ym >> (4 * g + 0)) & 1u) ? -1.0f : 1.0f;
        o.y = ((ym >> (4 * g + 1)) & 1u) ? -1.0f : 1.0f;
        o.z = ((ym >> (4 * g + 2)) & 1u) ? -1.0f : 1.0f;
        o.w = ((ym >> (4 * g + 3)) & 1u) ? -1.0f : 1.0f;
        o4[g] = o;
    }
}

// ---------------------------------------------------------------------------
extern "C" void kernel_launch(void* const* d_in, const int* in_sizes, int n_in,
                              void* d_out, int out_size)
{
    const float* x     = (const float*)d_in[0];
    const float* W     = (const float*)d_in[1];
    const int*   perms = (const int*)  d_in[2];
    float*       out   = (float*)d_out;

    const int B     = in_sizes[0] / NN;
    const int iters = in_sizes[2] / in_sizes[0];

    prep_wq<<<NN * NN / (256 * 16), 256>>>(W, x, B);
    gemv_init<<<NN, 256>>>(B);
    hopfield_seq<<<B, TPB>>>(x, perms, out, iters);
}